// round 1
// baseline (speedup 1.0000x reference)
#include <cuda_runtime.h>
#include <math.h>

// Problem constants (fixed shapes for this problem instance)
#define NTOK 65536   // B * Lq = 4 * 16384
#define LQ   16384
#define DM   128
#define NHH  4
#define NPP  4
#define HDD  32
#define FFD  512
#define GW   128
#define GH   128

// ---------------- device scratch (static, no allocations) ----------------
__device__ __align__(16) float g_q[NTOK * DM];          // running query (33.5 MB)
__device__ __align__(16) float g_value[NTOK * DM];      // value tensor  (33.5 MB)
__device__ __align__(16) float g_attn[NTOK * DM];       // sampled attn  (33.5 MB)
__device__ __align__(16) float g_hidden[NTOK * FFD];    // FFN hidden    (128 MB)
__device__ float g_px[NTOK * NHH * NPP];                // sample x (pixel coords)
__device__ float g_py[NTOK * NHH * NPP];                // sample y
__device__ float g_aw[NTOK * NHH * NPP];                // softmaxed attn weights

// ---------------------------------------------------------------------------
// Kernel 1: sampling params. qin = q + pos; off = qin@so_w+so_b (32 outs),
// logits = qin@aw_w+aw_b (16 outs, softmax over groups of 4).
// px = (q % W) + off_x ; py = (q / W) + off_y  (align_corners=False algebra)
// Block: 256 threads handles 32 tokens.
// ---------------------------------------------------------------------------
__global__ void __launch_bounds__(256) params_kernel(
    const float* __restrict__ pos,
    const float* __restrict__ so_w, const float* __restrict__ so_b,
    const float* __restrict__ aw_w, const float* __restrict__ aw_b)
{
    __shared__ float Ws[DM * 48];     // combined [k][48] weights (24.0 KB)
    __shared__ float qs[DM * 33];     // qin transposed [k][tok], pad 33 (16.5 KB)
    __shared__ float outs[32 * 49];   // per-token 48 outputs (6.1 KB)

    const int tid = threadIdx.x;
    const int t0 = blockIdx.x * 32;

    // load combined weight matrix
    for (int i = tid; i < DM * 48; i += 256) {
        int k = i / 48, o = i % 48;
        Ws[i] = (o < 32) ? so_w[k * 32 + o] : aw_w[k * 16 + (o - 32)];
    }
    // load qin (transposed into smem)
    for (int i = tid; i < 32 * DM; i += 256) {
        int tok = i >> 7, k = i & 127;
        int gq = t0 + tok;
        qs[k * 33 + tok] = g_q[gq * DM + k] + pos[gq * DM + k];
    }
    __syncthreads();

    const int tok = tid >> 3;       // 0..31
    const int og  = tid & 7;        // 0..7 -> outputs og*6 .. og*6+5
    float acc[6];
#pragma unroll
    for (int j = 0; j < 6; j++) {
        int o = og * 6 + j;
        acc[j] = (o < 32) ? so_b[o] : aw_b[o - 32];
    }
#pragma unroll 8
    for (int k = 0; k < DM; k++) {
        float a = qs[k * 33 + tok];
#pragma unroll
        for (int j = 0; j < 6; j++)
            acc[j] += a * Ws[k * 48 + og * 6 + j];
    }
#pragma unroll
    for (int j = 0; j < 6; j++) outs[tok * 49 + og * 6 + j] = acc[j];
    __syncthreads();

    if (tid < 128) {
        int tk = tid >> 2, h = tid & 3;
        int gq = t0 + tk;
        // softmax over the 4 points of this head
        float lg0 = outs[tk * 49 + 32 + h * 4 + 0];
        float lg1 = outs[tk * 49 + 32 + h * 4 + 1];
        float lg2 = outs[tk * 49 + 32 + h * 4 + 2];
        float lg3 = outs[tk * 49 + 32 + h * 4 + 3];
        float m = fmaxf(fmaxf(lg0, lg1), fmaxf(lg2, lg3));
        float e0 = expf(lg0 - m), e1 = expf(lg1 - m), e2 = expf(lg2 - m), e3 = expf(lg3 - m);
        float inv = 1.0f / (e0 + e1 + e2 + e3);
        // pixel-space reference point
        float jx = (float)(gq & (GW - 1));
        float iy = (float)((gq >> 7) & (GH - 1));
        int pbase = gq * 16 + h * 4;
#pragma unroll
        for (int p = 0; p < 4; p++) {
            g_px[pbase + p] = jx + outs[tk * 49 + h * 8 + p * 2 + 0];
            g_py[pbase + p] = iy + outs[tk * 49 + h * 8 + p * 2 + 1];
        }
        g_aw[pbase + 0] = e0 * inv;
        g_aw[pbase + 1] = e1 * inv;
        g_aw[pbase + 2] = e2 * inv;
        g_aw[pbase + 3] = e3 * inv;
    }
}

// ---------------------------------------------------------------------------
// Tiled fp32 GEMM: out[M][Ntot] = A[M][K] @ Wt[K][Ntot] + bias, optional ReLU,
// optional fused residual + LayerNorm (requires Ntot==128 covered by one block
// column, i.e. grid.y == 1). Tile 64 x 128, BK = 16, 256 threads, 8x4 per thr.
// Row ownership: warp w owns rows w*8..w*8+7; lane owns cols lane*4..lane*4+3
// -> full 128-wide row lives in one warp, LN via shuffle reduction.
// ---------------------------------------------------------------------------
template<int K, bool RELU, bool LN>
__global__ void __launch_bounds__(256) gemm_k(
    const float* __restrict__ A, const float* __restrict__ Wt,
    const float* __restrict__ bias, const float* __restrict__ resid,
    const float* __restrict__ lng, const float* __restrict__ lnb,
    float* __restrict__ out, int Ntot)
{
    __shared__ float As[16 * 65];                 // [k][row], padded
    __shared__ __align__(16) float Bs[16 * 128];  // [k][n]

    const int tid  = threadIdx.x;
    const int row0 = blockIdx.x * 64;
    const int n0   = blockIdx.y * 128;
    const int warp = tid >> 5, lane = tid & 31;

    float acc[8][4];
#pragma unroll
    for (int i = 0; i < 8; i++)
#pragma unroll
        for (int j = 0; j < 4; j++) acc[i][j] = 0.0f;

    const int arow = tid >> 2;            // 0..63
    const int akk  = (tid & 3) * 4;       // 0,4,8,12
    const float* Aptr = A + (size_t)(row0 + arow) * K + akk;

    for (int kt = 0; kt < K; kt += 16) {
        // A tile (vectorized load, transposed store)
        float4 av = *(const float4*)(Aptr + kt);
        As[(akk + 0) * 65 + arow] = av.x;
        As[(akk + 1) * 65 + arow] = av.y;
        As[(akk + 2) * 65 + arow] = av.z;
        As[(akk + 3) * 65 + arow] = av.w;
        // B tile (row-major, coalesced)
#pragma unroll
        for (int i = 0; i < 8; i++) {
            int idx = tid + i * 256;           // 0..2047
            int bk = idx >> 7, bn = idx & 127;
            Bs[bk * 128 + bn] = Wt[(size_t)(kt + bk) * Ntot + n0 + bn];
        }
        __syncthreads();
#pragma unroll
        for (int k = 0; k < 16; k++) {
            float4 b4 = *(const float4*)&Bs[k * 128 + lane * 4];
#pragma unroll
            for (int i = 0; i < 8; i++) {
                float a = As[k * 65 + warp * 8 + i];
                acc[i][0] += a * b4.x;
                acc[i][1] += a * b4.y;
                acc[i][2] += a * b4.z;
                acc[i][3] += a * b4.w;
            }
        }
        __syncthreads();
    }

    float4 bv = *(const float4*)&bias[n0 + lane * 4];

    if (LN) {
        float4 gv  = *(const float4*)&lng[lane * 4];
        float4 bev = *(const float4*)&lnb[lane * 4];
#pragma unroll
        for (int i = 0; i < 8; i++) {
            int r = row0 + warp * 8 + i;
            float4 rs = *(const float4*)&resid[(size_t)r * 128 + lane * 4];
            float v0 = acc[i][0] + bv.x + rs.x;
            float v1 = acc[i][1] + bv.y + rs.y;
            float v2 = acc[i][2] + bv.z + rs.z;
            float v3 = acc[i][3] + bv.w + rs.w;
            float s  = v0 + v1 + v2 + v3;
            float s2 = v0 * v0 + v1 * v1 + v2 * v2 + v3 * v3;
#pragma unroll
            for (int o = 16; o > 0; o >>= 1) {
                s  += __shfl_xor_sync(0xffffffffu, s,  o);
                s2 += __shfl_xor_sync(0xffffffffu, s2, o);
            }
            float mean = s * 0.0078125f;                 // /128
            float var  = s2 * 0.0078125f - mean * mean;
            float inv  = rsqrtf(var + 1e-5f);
            float4 o4;
            o4.x = (v0 - mean) * inv * gv.x + bev.x;
            o4.y = (v1 - mean) * inv * gv.y + bev.y;
            o4.z = (v2 - mean) * inv * gv.z + bev.z;
            o4.w = (v3 - mean) * inv * gv.w + bev.w;
            *(float4*)&out[(size_t)r * 128 + lane * 4] = o4;
        }
    } else {
#pragma unroll
        for (int i = 0; i < 8; i++) {
            int r = row0 + warp * 8 + i;
            float4 o4;
            o4.x = acc[i][0] + bv.x;
            o4.y = acc[i][1] + bv.y;
            o4.z = acc[i][2] + bv.z;
            o4.w = acc[i][3] + bv.w;
            if (RELU) {
                o4.x = fmaxf(o4.x, 0.0f); o4.y = fmaxf(o4.y, 0.0f);
                o4.z = fmaxf(o4.z, 0.0f); o4.w = fmaxf(o4.w, 0.0f);
            }
            *(float4*)&out[(size_t)r * Ntot + n0 + lane * 4] = o4;
        }
    }
}

// ---------------------------------------------------------------------------
// Kernel 3: bilinear sampling + attention-weighted sum.
// One warp per (token, head); lane = channel (HD=32). 4 points x 4 corners of
// coalesced 128B gathers from the value plane (zeros padding, exact match to
// grid_sample align_corners=False / padding_mode='zeros').
// ---------------------------------------------------------------------------
__global__ void __launch_bounds__(256) sample_kernel()
{
    const int gw   = (blockIdx.x * blockDim.x + threadIdx.x) >> 5;
    const int lane = threadIdx.x & 31;
    const int tok  = gw >> 2;         // 0..65535
    const int h    = gw & 3;
    const int b    = tok >> 14;

    const float* vplane = g_value + (size_t)(b * LQ) * DM + h * HDD;
    const int pbase = tok * 16 + h * 4;

    float acc = 0.0f;
#pragma unroll
    for (int p = 0; p < 4; p++) {
        float px = g_px[pbase + p];
        float py = g_py[pbase + p];
        float aw = g_aw[pbase + p];
        float fx = floorf(px), fy = floorf(py);
        int x0 = (int)fx, y0 = (int)fy;
        float wx = px - fx, wy = py - fy;
        float w00 = (1.0f - wx) * (1.0f - wy) * aw;
        float w10 = wx * (1.0f - wy) * aw;
        float w01 = (1.0f - wx) * wy * aw;
        float w11 = wx * wy * aw;

        int x1 = x0 + 1, y1 = y0 + 1;
        bool bx0 = (x0 >= 0) & (x0 < GW);
        bool bx1 = (x1 >= 0) & (x1 < GW);
        bool by0 = (y0 >= 0) & (y0 < GH);
        bool by1 = (y1 >= 0) & (y1 < GH);

        if (bx0 & by0) acc += w00 * vplane[(size_t)(y0 * GW + x0) * DM + lane];
        if (bx1 & by0) acc += w10 * vplane[(size_t)(y0 * GW + x1) * DM + lane];
        if (bx0 & by1) acc += w01 * vplane[(size_t)(y1 * GW + x0) * DM + lane];
        if (bx1 & by1) acc += w11 * vplane[(size_t)(y1 * GW + x1) * DM + lane];
    }
    g_attn[(size_t)tok * DM + h * HDD + lane] = acc;
}

// ---------------------------------------------------------------------------
extern "C" void kernel_launch(void* const* d_in, const int* in_sizes, int n_in,
                              void* d_out, int out_size)
{
    const float* query = (const float*)d_in[0];
    const float* src   = (const float*)d_in[1];
    const float* pos   = (const float*)d_in[2];
    const float* so_w  = (const float*)d_in[3];
    const float* so_b  = (const float*)d_in[4];
    const float* aw_w  = (const float*)d_in[5];
    const float* aw_b  = (const float*)d_in[6];
    const float* vp_w  = (const float*)d_in[7];
    const float* vp_b  = (const float*)d_in[8];
    const float* op_w  = (const float*)d_in[9];
    const float* op_b  = (const float*)d_in[10];
    const float* ln1_g = (const float*)d_in[11];
    const float* ln1_b = (const float*)d_in[12];
    const float* l1_w  = (const float*)d_in[13];
    const float* l1_b  = (const float*)d_in[14];
    const float* l2_w  = (const float*)d_in[15];
    const float* l2_b  = (const float*)d_in[16];
    const float* ln2_g = (const float*)d_in[17];
    const float* ln2_b = (const float*)d_in[18];
    // d_in[19], d_in[20] = H, W (constant 128, hardcoded)

    float *qbuf, *vbuf, *abuf, *hbuf;
    cudaGetSymbolAddress((void**)&qbuf, g_q);
    cudaGetSymbolAddress((void**)&vbuf, g_value);
    cudaGetSymbolAddress((void**)&abuf, g_attn);
    cudaGetSymbolAddress((void**)&hbuf, g_hidden);

    cudaMemcpyAsync(qbuf, query, sizeof(float) * (size_t)NTOK * DM,
                    cudaMemcpyDeviceToDevice, 0);

    for (int l = 0; l < 2; l++) {
        // 1) sampling locations + softmaxed weights
        params_kernel<<<NTOK / 32, 256>>>(pos,
                                          so_w + (size_t)l * DM * 32, so_b + l * 32,
                                          aw_w + (size_t)l * DM * 16, aw_b + l * 16);
        // 2) value projection: src @ vp_w + vp_b
        gemm_k<128, false, false><<<dim3(NTOK / 64, 1), 256>>>(
            src, vp_w + (size_t)l * DM * DM, vp_b + l * DM,
            nullptr, nullptr, nullptr, vbuf, 128);
        // 3) deformable sampling -> attn
        sample_kernel<<<(NTOK * NHH) / 8, 256>>>();
        // 4) output projection + residual + LN1 (in-place into q)
        gemm_k<128, false, true><<<dim3(NTOK / 64, 1), 256>>>(
            abuf, op_w + (size_t)l * DM * DM, op_b + l * DM,
            qbuf, ln1_g + l * DM, ln1_b + l * DM, qbuf, 128);
        // 5) FFN up: relu(q @ l1_w + l1_b)
        gemm_k<128, true, false><<<dim3(NTOK / 64, 4), 256>>>(
            qbuf, l1_w + (size_t)l * DM * FFD, l1_b + l * FFD,
            nullptr, nullptr, nullptr, hbuf, FFD);
        // 6) FFN down + residual + LN2 (in-place into q)
        gemm_k<512, false, true><<<dim3(NTOK / 64, 1), 256>>>(
            hbuf, l2_w + (size_t)l * FFD * DM, l2_b + l * DM,
            qbuf, ln2_g + l * DM, ln2_b + l * DM, qbuf, 128);
    }

    cudaMemcpyAsync(d_out, qbuf, sizeof(float) * (size_t)NTOK * DM,
                    cudaMemcpyDeviceToDevice, 0);
}